// round 14
// baseline (speedup 1.0000x reference)
#include <cuda_runtime.h>
#include <math.h>

#define NN 200000
#define NE 3200000
#define NG 1000
#define KP 30
#define CC 97
#define NBN 782            // ceil(NN/256)
#define MAXSORT 2048
#define FULLM 0xffffffffu

typedef unsigned long long ull;

// ---------------- device scratch ----------------
// self-cleaning atomic scratch: [0,NN) = deg, [NN,NN+NG) = graph cnt,
// [NN+NG] = rowstart cursor. Zero-init at load; each replay re-zeroes it.
__device__ int   g_zero[NN + NG + 1];
__device__ int   g_degc[NN];             // stable copy of degrees
__device__ int   g_cntc[NG];             // stable copy of graph counts
__device__ float g_invsqrt[NN];
__device__ float g_sqrtdeg[NN];
__device__ int   g_rowstart[NN];
__device__ int   g_epos[NE];             // per-edge slot within dst bucket
__device__ int   g_esrc[NE];             // CSR payload: src index only
__device__ float g_eye[32 * 32];         // identity for layer-1 via gathergemm
__device__ __align__(16) float g_hw[NN * 32];   // layer-1 rows
__device__ __align__(16) float g_hw4[NN];
__device__ __align__(16) float g_x1[NN * 32];   // premultiplied tanh outputs
__device__ __align__(16) float g_x2[NN * 32];
__device__ __align__(16) float g_x3[NN * 32];
__device__ __align__(16) float g_x4[NN];        // raw (final layer)
__device__ int g_start[NG];

// ---------------- fp32x2 packed math ----------------
__device__ __forceinline__ ull pk2(float a, float b) {
    ull r;
    asm("mov.b64 %0, {%1, %2};" : "=l"(r) : "f"(a), "f"(b));
    return r;
}
__device__ __forceinline__ ull ffma2(ull a, ull b, ull c) {
    ull d;
    asm("fma.rn.f32x2 %0, %1, %2, %3;" : "=l"(d) : "l"(a), "l"(b), "l"(c));
    return d;
}
__device__ __forceinline__ float2 upk2(ull a) {
    float x, y;
    asm("mov.b64 {%0, %1}, %2;" : "=f"(x), "=f"(y) : "l"(a));
    return make_float2(x, y);
}

// ===== fused: edge degree atomics + per-graph counts + layer-1 GEMM (raw) =====
__global__ void __launch_bounds__(256) k_all1(
    const int* __restrict__ ei, const int* __restrict__ batch,
    const float* __restrict__ x, const float* __restrict__ W,
    float* __restrict__ hw) {
    __shared__ float sW[128 * 32];
    int tid = threadIdx.x;
    int i = blockIdx.x * 256 + tid;

    if (blockIdx.x < NBN) {
        for (int k = tid; k < 128 * 32; k += 256) sW[k] = W[k];
    }
    __syncthreads();

    int e4 = i * 4;
    int4 s, d;
    int p0 = 0, p1 = 0, p2 = 0, p3 = 0;
    bool has_edge = (e4 < NE);
    if (has_edge) {
        s = __ldg((const int4*)(ei + e4));
        d = __ldg((const int4*)(ei + NE + e4));
        if (s.x != d.x) p0 = atomicAdd(&g_zero[d.x], 1);
        if (s.y != d.y) p1 = atomicAdd(&g_zero[d.y], 1);
        if (s.z != d.z) p2 = atomicAdd(&g_zero[d.z], 1);
        if (s.w != d.w) p3 = atomicAdd(&g_zero[d.w], 1);
    }
    if (i < NN) atomicAdd(&g_zero[NN + batch[i]], 1);

    if (blockIdx.x < NBN && i < NN) {
        ull acc[16];
#pragma unroll
        for (int j = 0; j < 16; j++) acc[j] = 0ull;
        const float4* hr = (const float4*)(x + (size_t)i * 128);
#pragma unroll 4
        for (int k4 = 0; k4 < 32; k4++) {
            float4 v = hr[k4];
            const float* hk = &v.x;
#pragma unroll
            for (int kk = 0; kk < 4; kk++) {
                ull hv2 = pk2(hk[kk], hk[kk]);
                const float4* wr = (const float4*)&sW[(k4 * 4 + kk) * 32];
#pragma unroll
                for (int q = 0; q < 8; q++) {
                    float4 w = wr[q];
                    acc[2 * q]     = ffma2(hv2, pk2(w.x, w.y), acc[2 * q]);
                    acc[2 * q + 1] = ffma2(hv2, pk2(w.z, w.w), acc[2 * q + 1]);
                }
            }
        }
        float4* hwv = (float4*)(hw + (size_t)i * 32);
#pragma unroll
        for (int q = 0; q < 8; q++) {
            float2 a = upk2(acc[2 * q]);
            float2 bq = upk2(acc[2 * q + 1]);
            hwv[q] = make_float4(a.x, a.y, bq.x, bq.y);
        }
    }

    if (has_edge) *((int4*)(g_epos + e4)) = make_int4(p0, p1, p2, p3);
}

// ===== prep: read+ZERO deg/cnt, invsqrt/sqrtdeg, atomic rowstart, hw*=isq;
//       block0: graph scan; block1: write identity matrix
__global__ void __launch_bounds__(256) k_prep2(float* __restrict__ hw) {
    int tid = threadIdx.x;
    int i = blockIdx.x * 256 + tid;
    if (i < NN) {
        int dI = g_zero[i];
        g_zero[i] = 0;                    // self-clean for next replay
        g_degc[i] = dI;
        float dg = (float)dI + 1.0f;
        float is = rsqrtf(dg);
        g_invsqrt[i] = is;
        g_sqrtdeg[i] = dg * is;
        g_rowstart[i] = atomicAdd(&g_zero[NN + NG], dI);
        float4* r = (float4*)(hw + (size_t)i * 32);
#pragma unroll
        for (int q = 0; q < 8; q++) {
            float4 v = r[q];
            v.x *= is; v.y *= is; v.z *= is; v.w *= is;
            r[q] = v;
        }
    }
    if (blockIdx.x == 0) {
        __shared__ int ts[256];
        int base = tid * 4;
        int a0 = (base < NG)     ? g_zero[NN + base]     : 0;
        int a1 = (base + 1 < NG) ? g_zero[NN + base + 1] : 0;
        int a2 = (base + 2 < NG) ? g_zero[NN + base + 2] : 0;
        int a3 = (base + 3 < NG) ? g_zero[NN + base + 3] : 0;
        if (base < NG)     g_zero[NN + base]     = 0;   // self-clean
        if (base + 1 < NG) g_zero[NN + base + 1] = 0;
        if (base + 2 < NG) g_zero[NN + base + 2] = 0;
        if (base + 3 < NG) g_zero[NN + base + 3] = 0;
        int s1 = a0 + a1, s2 = s1 + a2, tot = s2 + a3;
        ts[tid] = tot;
        __syncthreads();
        for (int off = 1; off < 256; off <<= 1) {
            int v = (tid >= off) ? ts[tid - off] : 0;
            __syncthreads();
            ts[tid] += v;
            __syncthreads();
        }
        int ex = ts[tid] - tot;
        if (base < NG)     { g_start[base]     = ex;      g_cntc[base]     = a0; }
        if (base + 1 < NG) { g_start[base + 1] = ex + a0; g_cntc[base + 1] = a1; }
        if (base + 2 < NG) { g_start[base + 2] = ex + s1; g_cntc[base + 2] = a2; }
        if (base + 3 < NG) { g_start[base + 3] = ex + s2; g_cntc[base + 3] = a3; }
    }
    if (blockIdx.x == 1) {
        // identity matrix for the layer-1 gathergemm
        for (int k = tid; k < 32 * 32; k += 256)
            g_eye[k] = ((k >> 5) == (k & 31)) ? 1.0f : 0.0f;
    }
}

// atomic-free CSR fill using recorded slots
__global__ void k_fill(const int* __restrict__ ei) {
    int i = blockIdx.x * blockDim.x + threadIdx.x;
    int e4 = i * 4;
    if (e4 >= NE) return;
    int4 s = __ldg((const int4*)(ei + e4));
    int4 d = __ldg((const int4*)(ei + NE + e4));
    int4 p = *((const int4*)(g_epos + e4));
    if (s.x != d.x) g_esrc[g_rowstart[d.x] + p.x] = s.x;
    if (s.y != d.y) g_esrc[g_rowstart[d.y] + p.y] = s.y;
    if (s.z != d.z) g_esrc[g_rowstart[d.z] + p.z] = s.z;
    if (s.w != d.w) g_esrc[g_rowstart[d.w] + p.w] = s.w;
}

// ---- 4-edge x float4 plain-sum aggregation (incl. self row), MLP=8 unroll ----
__device__ __forceinline__ float4 agg_sum(const float* __restrict__ in, int node,
                                          int g, int q) {
    int rs = g_rowstart[node];
    int re = rs + g_degc[node];      // deg
    float4 acc = __ldg((const float4*)(in + (size_t)node * 32 + q * 4)); // self
    if (g != 0) acc = make_float4(0.f, 0.f, 0.f, 0.f);
    int e = rs;
    for (; e + 8 <= re; e += 8) {
        int s0 = __ldg(&g_esrc[e + g]);
        int s1 = __ldg(&g_esrc[e + 4 + g]);
        float4 v0 = __ldg((const float4*)(in + (size_t)s0 * 32 + q * 4));
        float4 v1 = __ldg((const float4*)(in + (size_t)s1 * 32 + q * 4));
        acc.x += v0.x + v1.x; acc.y += v0.y + v1.y;
        acc.z += v0.z + v1.z; acc.w += v0.w + v1.w;
    }
    if (e + 4 <= re) {
        int s0 = __ldg(&g_esrc[e + g]);
        float4 v0 = __ldg((const float4*)(in + (size_t)s0 * 32 + q * 4));
        acc.x += v0.x; acc.y += v0.y; acc.z += v0.z; acc.w += v0.w;
        e += 4;
    }
    int rem = re - e;
    if (g < rem) {
        int s0 = __ldg(&g_esrc[e + g]);
        float4 v0 = __ldg((const float4*)(in + (size_t)s0 * 32 + q * 4));
        acc.x += v0.x; acc.y += v0.y; acc.z += v0.z; acc.w += v0.w;
    }
#pragma unroll
    for (int off = 8; off <= 16; off <<= 1) {
        acc.x += __shfl_xor_sync(FULLM, acc.x, off);
        acc.y += __shfl_xor_sync(FULLM, acc.y, off);
        acc.z += __shfl_xor_sync(FULLM, acc.z, off);
        acc.w += __shfl_xor_sync(FULLM, acc.w, off);
    }
    return acc;
}

// ------------- fused gather+GEMM (layers 1,2,3): y = tanh((isq*acc)@W + b)*isq -
// Layer 1 passes W = identity (math reduces to tanh(isq*acc + b)*isq).
// If w4 != nullptr, also emit g_hw4[node] = (y_premult . W4).
__global__ void __launch_bounds__(256) k_gathergemm(
    const float* __restrict__ in, const float* __restrict__ W,
    const float* __restrict__ b, float* __restrict__ out,
    const float* __restrict__ w4, int nwarps) {
    int lane = threadIdx.x & 31;
    int wid  = (blockIdx.x * blockDim.x + threadIdx.x) >> 5;
    int g = lane >> 3, q = lane & 7;
    ull Wp[16];
#pragma unroll
    for (int c = 0; c < 16; c++)
        Wp[c] = pk2(__ldg(&W[(2 * c) * 32 + lane]), __ldg(&W[(2 * c + 1) * 32 + lane]));
    float bias = __ldg(&b[lane]);
    float w4l = w4 ? __ldg(&w4[lane]) : 0.f;

    for (int node = wid; node < NN; node += nwarps) {
        float4 acc = agg_sum(in, node, g, q);
        float isq = g_invsqrt[node];
        acc.x *= isq; acc.y *= isq; acc.z *= isq; acc.w *= isq;
        ull o2 = pk2(bias, 0.f);
#pragma unroll
        for (int c = 0; c < 32; c += 2) {
            float va, vb;
            {
                float comp = ((c & 3) == 0) ? acc.x : ((c & 3) == 1) ? acc.y :
                             ((c & 3) == 2) ? acc.z : acc.w;
                va = __shfl_sync(FULLM, comp, c >> 2);
            }
            {
                int c1 = c + 1;
                float comp = ((c1 & 3) == 0) ? acc.x : ((c1 & 3) == 1) ? acc.y :
                             ((c1 & 3) == 2) ? acc.z : acc.w;
                vb = __shfl_sync(FULLM, comp, c1 >> 2);
            }
            o2 = ffma2(pk2(va, vb), Wp[c >> 1], o2);
        }
        float2 oo = upk2(o2);
        float o = tanhf(oo.x + oo.y) * isq;            // premultiplied output
        out[(size_t)node * 32 + lane] = o;
        if (w4) {
            float v = o * w4l;
#pragma unroll
            for (int off = 16; off > 0; off >>= 1)
                v += __shfl_xor_sync(FULLM, v, off);
            if (lane == 0) g_hw4[node] = v;
        }
    }
}

// ---------------- layer-4 gather (scalar): x4 = tanh(isq*acc + b4) ------------
__global__ void k_gather1(const float* __restrict__ b4) {
    int node = blockIdx.x * blockDim.x + threadIdx.x;
    if (node == 0) g_zero[NN + NG] = 0;   // self-clean cursor for next replay
    if (node >= NN) return;
    int rs = g_rowstart[node];
    int re = rs + g_degc[node];
    float acc = g_hw4[node];   // self
    int e = rs;
    for (; e + 4 <= re; e += 4) {
        int s0 = __ldg(&g_esrc[e]);
        int s1 = __ldg(&g_esrc[e + 1]);
        int s2 = __ldg(&g_esrc[e + 2]);
        int s3 = __ldg(&g_esrc[e + 3]);
        acc += g_hw4[s0] + g_hw4[s1] + g_hw4[s2] + g_hw4[s3];
    }
    for (; e < re; e++) acc += g_hw4[__ldg(&g_esrc[e])];
    g_x4[node] = tanhf(acc * g_invsqrt[node] + __ldg(&b4[0]));
}

// ---------------- sort-pool + CNN/FC head ----------------
__global__ void __launch_bounds__(128) k_head(
    const float* __restrict__ w5, const float* __restrict__ b5,
    const float* __restrict__ w6, const float* __restrict__ b6,
    const float* __restrict__ fw1, const float* __restrict__ fb1,
    const float* __restrict__ fw2, const float* __restrict__ fb2,
    float* __restrict__ out) {
    const int T = 128;
    int g = blockIdx.x;
    int tid = threadIdx.x;

    __shared__ unsigned long long keys[MAXSORT];
    __shared__ float pooled[KP * CC];
    __shared__ float z5[16 * 30];
    __shared__ float p5[16 * 15];
    __shared__ float z6[352];
    __shared__ float h1[128];
    __shared__ float logits[10];
    __shared__ int   seln[KP];
    __shared__ float bestv[128];
    __shared__ int   besti[128];

    int start = g_start[g];
    int cnt   = g_cntc[g];
    int kk = cnt < KP ? cnt : KP;

    for (int i = tid; i < KP * CC; i += T) pooled[i] = 0.f;

    if (cnt <= MAXSORT) {
        int n2 = 1;
        while (n2 < cnt) n2 <<= 1;
        for (int i = tid; i < n2; i += T) {
            if (i < cnt) {
                unsigned u = __float_as_uint(g_x4[start + i]);
                u ^= (u >> 31) ? 0xFFFFFFFFu : 0x80000000u;
                u = ~u;
                keys[i] = ((unsigned long long)u << 32) | (unsigned)(start + i);
            } else {
                keys[i] = 0xFFFFFFFFFFFFFFFFull;
            }
        }
        __syncthreads();
        for (int k = 2; k <= n2; k <<= 1) {
            for (int j = k >> 1; j > 0; j >>= 1) {
                for (int i = tid; i < n2; i += T) {
                    int ixj = i ^ j;
                    if (ixj > i) {
                        bool up = ((i & k) == 0);
                        unsigned long long a = keys[i], bk = keys[ixj];
                        if ((a > bk) == up) { keys[i] = bk; keys[ixj] = a; }
                    }
                }
                __syncthreads();
            }
        }
        for (int r = tid; r < kk; r += T)
            seln[r] = (int)(keys[r] & 0xffffffffull);
        __syncthreads();
    } else {
        __shared__ float pv_s;
        __shared__ int pidx_s;
        if (tid == 0) { pv_s = 3.0e38f; pidx_s = -1; }
        __syncthreads();
        for (int r = 0; r < kk; r++) {
            float lpv = pv_s; int lpidx = pidx_s;
            float bv = -3.0e38f; int bi = 0x7fffffff;
            for (int i = start + tid; i < start + cnt; i += T) {
                float v = g_x4[i];
                bool after = (v < lpv) || (v == lpv && i > lpidx);
                if (after && ((v > bv) || (v == bv && i < bi))) { bv = v; bi = i; }
            }
            bestv[tid] = bv; besti[tid] = bi;
            __syncthreads();
            for (int sft = T / 2; sft > 0; sft >>= 1) {
                if (tid < sft) {
                    float ov = bestv[tid + sft]; int oi = besti[tid + sft];
                    if ((ov > bestv[tid]) || (ov == bestv[tid] && oi < besti[tid])) {
                        bestv[tid] = ov; besti[tid] = oi;
                    }
                }
                __syncthreads();
            }
            if (tid == 0) { seln[r] = besti[0]; pv_s = bestv[0]; pidx_s = besti[0]; }
            __syncthreads();
        }
    }

    // gather pooled rows [kk x 97] (un-premultiply with sqrtdeg)
    for (int idx = tid; idx < kk * CC; idx += T) {
        int r = idx / CC, c = idx % CC;
        int node = seln[r];
        float val;
        if (c < 96) {
            float sq = g_sqrtdeg[node];
            if (c < 32)      val = g_x1[(size_t)node * 32 + c] * sq;
            else if (c < 64) val = g_x2[(size_t)node * 32 + (c - 32)] * sq;
            else             val = g_x3[(size_t)node * 32 + (c - 64)] * sq;
        } else {
            val = g_x4[node];
        }
        pooled[r * CC + c] = val;
    }
    __syncthreads();

    for (int idx = tid; idx < 16 * 30; idx += T) {
        int oc = idx / 30, t = idx % 30;
        float s = b5[oc];
        const float* wr = &w5[oc * 97];
        const float* pr = &pooled[t * 97];
        for (int c = 0; c < 97; c++) s += pr[c] * wr[c];
        z5[oc * 30 + t] = fmaxf(s, 0.f);
    }
    __syncthreads();
    for (int idx = tid; idx < 16 * 15; idx += T) {
        int oc = idx / 15, u = idx % 15;
        p5[idx] = fmaxf(z5[oc * 30 + 2 * u], z5[oc * 30 + 2 * u + 1]);
    }
    __syncthreads();
    for (int idx = tid; idx < 352; idx += T) {
        int oc = idx / 11, v = idx % 11;
        float s = b6[oc];
        for (int ic = 0; ic < 16; ic++) {
            const float* wr = &w6[oc * 80 + ic * 5];
            const float* pr = &p5[ic * 15 + v];
#pragma unroll
            for (int qq = 0; qq < 5; qq++) s += pr[qq] * wr[qq];
        }
        z6[idx] = fmaxf(s, 0.f);
    }
    __syncthreads();
    for (int j = tid; j < 128; j += T) {
        float s = fb1[j];
        for (int i = 0; i < 352; i++) s += z6[i] * fw1[i * 128 + j];
        h1[j] = fmaxf(s, 0.f);
    }
    __syncthreads();
    for (int c = tid; c < 10; c += T) {
        float s = fb2[c];
        for (int j = 0; j < 128; j++) s += h1[j] * fw2[j * 10 + c];
        logits[c] = s;
    }
    __syncthreads();
    if (tid == 0) {
        float mx = logits[0];
        for (int c = 1; c < 10; c++) mx = fmaxf(mx, logits[c]);
        float se = 0.f;
        for (int c = 0; c < 10; c++) se += expf(logits[c] - mx);
        float lse = logf(se) + mx;
        for (int c = 0; c < 10; c++) out[(size_t)g * 10 + c] = logits[c] - lse;
    }
}

// ---------------- launch ----------------
extern "C" void kernel_launch(void* const* d_in, const int* in_sizes, int n_in,
                              void* d_out, int out_size) {
    const float* x      = (const float*)d_in[0];
    const int*   ei     = (const int*)d_in[1];
    const int*   batch  = (const int*)d_in[2];
    const float* W1 = (const float*)d_in[3];  const float* b1 = (const float*)d_in[4];
    const float* W2 = (const float*)d_in[5];  const float* b2 = (const float*)d_in[6];
    const float* W3 = (const float*)d_in[7];  const float* b3 = (const float*)d_in[8];
    const float* W4 = (const float*)d_in[9];  const float* b4 = (const float*)d_in[10];
    const float* w5 = (const float*)d_in[11]; const float* b5 = (const float*)d_in[12];
    const float* w6 = (const float*)d_in[13]; const float* b6 = (const float*)d_in[14];
    const float* fw1 = (const float*)d_in[15]; const float* fb1 = (const float*)d_in[16];
    const float* fw2 = (const float*)d_in[17]; const float* fb2 = (const float*)d_in[18];
    float* out = (float*)d_out;

    void *p_hw, *p_x1, *p_x2, *p_x3, *p_eye;
    cudaGetSymbolAddress(&p_hw, g_hw);
    cudaGetSymbolAddress(&p_x1, g_x1);
    cudaGetSymbolAddress(&p_x2, g_x2);
    cudaGetSymbolAddress(&p_x3, g_x3);
    cudaGetSymbolAddress(&p_eye, g_eye);
    float* hw = (float*)p_hw;
    float* x1 = (float*)p_x1;
    float* x2 = (float*)p_x2;
    float* x3 = (float*)p_x3;
    const float* eye = (const float*)p_eye;

    const int TB = 256;
    const int NB_N = NBN;
    const int NB_E4 = (NE / 4 + TB - 1) / TB;     // 3125
    const int GG_BLOCKS = 1184;                   // 8 blocks/SM * 148
    const int GG_WARPS  = GG_BLOCKS * (TB / 32);

    k_all1<<<NB_E4, TB>>>(ei, batch, x, W1, hw);
    k_prep2<<<NB_N, TB>>>(hw);
    k_fill<<<NB_E4, TB>>>(ei);
    // layers 1,2,3 all via the same fused gather+GEMM (layer 1 with identity W)
    k_gathergemm<<<GG_BLOCKS, TB>>>(hw, eye, b1, x1, nullptr, GG_WARPS);
    k_gathergemm<<<GG_BLOCKS, TB>>>(x1, W2, b2, x2, nullptr, GG_WARPS);
    k_gathergemm<<<GG_BLOCKS, TB>>>(x2, W3, b3, x3, W4, GG_WARPS);
    k_gather1<<<NB_N, TB>>>(b4);
    k_head<<<NG, 128>>>(w5, b5, w6, b6, fw1, fb1, fw2, fb2, out);
}

// round 15
// speedup vs baseline: 1.0323x; 1.0323x over previous
#include <cuda_runtime.h>
#include <math.h>

#define NN 200000
#define NE 3200000
#define NG 1000
#define KP 30
#define CC 97
#define NBN 782            // ceil(NN/256)
#define MAXSORT 2048
#define FULLM 0xffffffffu

typedef unsigned long long ull;

// ---------------- device scratch ----------------
// self-cleaning atomic scratch: [0,NN) = deg, [NN,NN+NG) = graph cnt,
// [NN+NG] = rowstart cursor. Zero-init at load; each replay re-zeroes it.
__device__ int   g_zero[NN + NG + 1];
__device__ int   g_degc[NN];             // stable copy of degrees
__device__ int   g_cntc[NG];             // stable copy of graph counts
__device__ float g_invsqrt[NN];
__device__ float g_sqrtdeg[NN];
__device__ int   g_rowstart[NN];
__device__ int   g_epos[NE];             // per-edge slot within dst bucket
__device__ int   g_esrc[NE];             // CSR payload: src index only
__device__ __align__(16) float g_hw[NN * 32];   // layer-1 rows
__device__ __align__(16) float g_hw4[NN];
__device__ __align__(16) float g_x1[NN * 32];   // premultiplied tanh outputs
__device__ __align__(16) float g_x2[NN * 32];
__device__ __align__(16) float g_x3[NN * 32];
__device__ __align__(16) float g_x4[NN];        // raw (final layer)
__device__ int g_start[NG];

// ---------------- fp32x2 packed math ----------------
__device__ __forceinline__ ull pk2(float a, float b) {
    ull r;
    asm("mov.b64 %0, {%1, %2};" : "=l"(r) : "f"(a), "f"(b));
    return r;
}
__device__ __forceinline__ ull ffma2(ull a, ull b, ull c) {
    ull d;
    asm("fma.rn.f32x2 %0, %1, %2, %3;" : "=l"(d) : "l"(a), "l"(b), "l"(c));
    return d;
}
__device__ __forceinline__ float2 upk2(ull a) {
    float x, y;
    asm("mov.b64 {%0, %1}, %2;" : "=f"(x), "=f"(y) : "l"(a));
    return make_float2(x, y);
}

// ===== fused: edge degree atomics + per-graph counts + layer-1 GEMM (raw) =====
__global__ void __launch_bounds__(256) k_all1(
    const int* __restrict__ ei, const int* __restrict__ batch,
    const float* __restrict__ x, const float* __restrict__ W,
    float* __restrict__ hw) {
    __shared__ float sW[128 * 32];
    int tid = threadIdx.x;
    int i = blockIdx.x * 256 + tid;

    if (blockIdx.x < NBN) {
        for (int k = tid; k < 128 * 32; k += 256) sW[k] = W[k];
    }
    __syncthreads();

    int e4 = i * 4;
    int4 s, d;
    int p0 = 0, p1 = 0, p2 = 0, p3 = 0;
    bool has_edge = (e4 < NE);
    if (has_edge) {
        s = __ldg((const int4*)(ei + e4));
        d = __ldg((const int4*)(ei + NE + e4));
        if (s.x != d.x) p0 = atomicAdd(&g_zero[d.x], 1);
        if (s.y != d.y) p1 = atomicAdd(&g_zero[d.y], 1);
        if (s.z != d.z) p2 = atomicAdd(&g_zero[d.z], 1);
        if (s.w != d.w) p3 = atomicAdd(&g_zero[d.w], 1);
    }
    if (i < NN) atomicAdd(&g_zero[NN + batch[i]], 1);

    if (blockIdx.x < NBN && i < NN) {
        ull acc[16];
#pragma unroll
        for (int j = 0; j < 16; j++) acc[j] = 0ull;
        const float4* hr = (const float4*)(x + (size_t)i * 128);
#pragma unroll 4
        for (int k4 = 0; k4 < 32; k4++) {
            float4 v = hr[k4];
            const float* hk = &v.x;
#pragma unroll
            for (int kk = 0; kk < 4; kk++) {
                ull hv2 = pk2(hk[kk], hk[kk]);
                const float4* wr = (const float4*)&sW[(k4 * 4 + kk) * 32];
#pragma unroll
                for (int q = 0; q < 8; q++) {
                    float4 w = wr[q];
                    acc[2 * q]     = ffma2(hv2, pk2(w.x, w.y), acc[2 * q]);
                    acc[2 * q + 1] = ffma2(hv2, pk2(w.z, w.w), acc[2 * q + 1]);
                }
            }
        }
        float4* hwv = (float4*)(hw + (size_t)i * 32);
#pragma unroll
        for (int q = 0; q < 8; q++) {
            float2 a = upk2(acc[2 * q]);
            float2 bq = upk2(acc[2 * q + 1]);
            hwv[q] = make_float4(a.x, a.y, bq.x, bq.y);
        }
    }

    if (has_edge) *((int4*)(g_epos + e4)) = make_int4(p0, p1, p2, p3);
}

// ===== prep: read+ZERO deg/cnt, invsqrt/sqrtdeg, atomic rowstart, hw*=isq;
//       block0: graph scan into g_start + g_cntc
__global__ void __launch_bounds__(256) k_prep2(float* __restrict__ hw) {
    int tid = threadIdx.x;
    int i = blockIdx.x * 256 + tid;
    if (i < NN) {
        int dI = g_zero[i];
        g_zero[i] = 0;                    // self-clean for next replay
        g_degc[i] = dI;
        float dg = (float)dI + 1.0f;
        float is = rsqrtf(dg);
        g_invsqrt[i] = is;
        g_sqrtdeg[i] = dg * is;
        g_rowstart[i] = atomicAdd(&g_zero[NN + NG], dI);
        float4* r = (float4*)(hw + (size_t)i * 32);
#pragma unroll
        for (int q = 0; q < 8; q++) {
            float4 v = r[q];
            v.x *= is; v.y *= is; v.z *= is; v.w *= is;
            r[q] = v;
        }
    }
    if (blockIdx.x == 0) {
        __shared__ int ts[256];
        int base = tid * 4;
        int a0 = (base < NG)     ? g_zero[NN + base]     : 0;
        int a1 = (base + 1 < NG) ? g_zero[NN + base + 1] : 0;
        int a2 = (base + 2 < NG) ? g_zero[NN + base + 2] : 0;
        int a3 = (base + 3 < NG) ? g_zero[NN + base + 3] : 0;
        if (base < NG)     g_zero[NN + base]     = 0;   // self-clean
        if (base + 1 < NG) g_zero[NN + base + 1] = 0;
        if (base + 2 < NG) g_zero[NN + base + 2] = 0;
        if (base + 3 < NG) g_zero[NN + base + 3] = 0;
        int s1 = a0 + a1, s2 = s1 + a2, tot = s2 + a3;
        ts[tid] = tot;
        __syncthreads();
        for (int off = 1; off < 256; off <<= 1) {
            int v = (tid >= off) ? ts[tid - off] : 0;
            __syncthreads();
            ts[tid] += v;
            __syncthreads();
        }
        int ex = ts[tid] - tot;
        if (base < NG)     { g_start[base]     = ex;      g_cntc[base]     = a0; }
        if (base + 1 < NG) { g_start[base + 1] = ex + a0; g_cntc[base + 1] = a1; }
        if (base + 2 < NG) { g_start[base + 2] = ex + s1; g_cntc[base + 2] = a2; }
        if (base + 3 < NG) { g_start[base + 3] = ex + s2; g_cntc[base + 3] = a3; }
    }
}

// atomic-free CSR fill using recorded slots
__global__ void k_fill(const int* __restrict__ ei) {
    int i = blockIdx.x * blockDim.x + threadIdx.x;
    int e4 = i * 4;
    if (e4 >= NE) return;
    int4 s = __ldg((const int4*)(ei + e4));
    int4 d = __ldg((const int4*)(ei + NE + e4));
    int4 p = *((const int4*)(g_epos + e4));
    if (s.x != d.x) g_esrc[g_rowstart[d.x] + p.x] = s.x;
    if (s.y != d.y) g_esrc[g_rowstart[d.y] + p.y] = s.y;
    if (s.z != d.z) g_esrc[g_rowstart[d.z] + p.z] = s.z;
    if (s.w != d.w) g_esrc[g_rowstart[d.w] + p.w] = s.w;
}

// ---- 4-edge x float4 plain-sum aggregation (incl. self row), MLP=8 unroll ----
__device__ __forceinline__ float4 agg_sum(const float* __restrict__ in, int node,
                                          int g, int q) {
    int rs = g_rowstart[node];
    int re = rs + g_degc[node];      // deg
    float4 acc = __ldg((const float4*)(in + (size_t)node * 32 + q * 4)); // self
    if (g != 0) acc = make_float4(0.f, 0.f, 0.f, 0.f);
    int e = rs;
    for (; e + 8 <= re; e += 8) {
        int s0 = __ldg(&g_esrc[e + g]);
        int s1 = __ldg(&g_esrc[e + 4 + g]);
        float4 v0 = __ldg((const float4*)(in + (size_t)s0 * 32 + q * 4));
        float4 v1 = __ldg((const float4*)(in + (size_t)s1 * 32 + q * 4));
        acc.x += v0.x + v1.x; acc.y += v0.y + v1.y;
        acc.z += v0.z + v1.z; acc.w += v0.w + v1.w;
    }
    if (e + 4 <= re) {
        int s0 = __ldg(&g_esrc[e + g]);
        float4 v0 = __ldg((const float4*)(in + (size_t)s0 * 32 + q * 4));
        acc.x += v0.x; acc.y += v0.y; acc.z += v0.z; acc.w += v0.w;
        e += 4;
    }
    int rem = re - e;
    if (g < rem) {
        int s0 = __ldg(&g_esrc[e + g]);
        float4 v0 = __ldg((const float4*)(in + (size_t)s0 * 32 + q * 4));
        acc.x += v0.x; acc.y += v0.y; acc.z += v0.z; acc.w += v0.w;
    }
#pragma unroll
    for (int off = 8; off <= 16; off <<= 1) {
        acc.x += __shfl_xor_sync(FULLM, acc.x, off);
        acc.y += __shfl_xor_sync(FULLM, acc.y, off);
        acc.z += __shfl_xor_sync(FULLM, acc.z, off);
        acc.w += __shfl_xor_sync(FULLM, acc.w, off);
    }
    return acc;
}

// ---------------- layer-1 gather: y1 = tanh(isq*acc + b) * isq ----------------
// Epilogue: per-lane channel (full-warp tanh).
__global__ void __launch_bounds__(256) k_gather_q(
    const float* __restrict__ in, float* __restrict__ out,
    const float* __restrict__ b, int nwarps) {
    int lane = threadIdx.x & 31;
    int wid  = (blockIdx.x * blockDim.x + threadIdx.x) >> 5;
    int g = lane >> 3, q = lane & 7;
    float bias = __ldg(&b[lane]);        // channel `lane`
    int srcl = lane >> 2;                // lane holding quad (lane>>2) in group 0
    int m = lane & 3;
    for (int node = wid; node < NN; node += nwarps) {
        float4 acc = agg_sum(in, node, g, q);   // replicated across groups
        float v0 = __shfl_sync(FULLM, acc.x, srcl);
        float v1 = __shfl_sync(FULLM, acc.y, srcl);
        float v2 = __shfl_sync(FULLM, acc.z, srcl);
        float v3 = __shfl_sync(FULLM, acc.w, srcl);
        float v = (m == 0) ? v0 : (m == 1) ? v1 : (m == 2) ? v2 : v3;
        float isq = g_invsqrt[node];
        out[(size_t)node * 32 + lane] = tanhf(v * isq + bias) * isq;
    }
}

// ------------- fused gather+GEMM (layers 2,3): y = tanh((isq*acc)@W + b)*isq ---
// W kept in SHARED memory as packed f32x2 row-pairs: sWp[c2*32+lane] holds
// (W[2*c2][lane], W[2*c2+1][lane]). Keeps registers low (occupancy!).
__global__ void __launch_bounds__(256) k_gathergemm(
    const float* __restrict__ in, const float* __restrict__ W,
    const float* __restrict__ b, float* __restrict__ out,
    const float* __restrict__ w4, int nwarps) {
    __shared__ ull sWp[16 * 32];
    int tid = threadIdx.x;
    int lane = tid & 31;
    int wid  = (blockIdx.x * blockDim.x + tid) >> 5;
    int g = lane >> 3, q = lane & 7;
    // build packed weights once per block
    for (int k = tid; k < 16 * 32; k += 256) {
        int c2 = k >> 5, l = k & 31;
        sWp[k] = pk2(__ldg(&W[(2 * c2) * 32 + l]), __ldg(&W[(2 * c2 + 1) * 32 + l]));
    }
    float bias = __ldg(&b[lane]);
    float w4l = w4 ? __ldg(&w4[lane]) : 0.f;
    __syncthreads();

    for (int node = wid; node < NN; node += nwarps) {
        float4 acc = agg_sum(in, node, g, q);
        float isq = g_invsqrt[node];
        acc.x *= isq; acc.y *= isq; acc.z *= isq; acc.w *= isq;
        ull o2 = pk2(bias, 0.f);
#pragma unroll
        for (int c = 0; c < 32; c += 2) {
            float va, vb;
            {
                float comp = ((c & 3) == 0) ? acc.x : ((c & 3) == 1) ? acc.y :
                             ((c & 3) == 2) ? acc.z : acc.w;
                va = __shfl_sync(FULLM, comp, c >> 2);
            }
            {
                int c1 = c + 1;
                float comp = ((c1 & 3) == 0) ? acc.x : ((c1 & 3) == 1) ? acc.y :
                             ((c1 & 3) == 2) ? acc.z : acc.w;
                vb = __shfl_sync(FULLM, comp, c1 >> 2);
            }
            o2 = ffma2(pk2(va, vb), sWp[(c >> 1) * 32 + lane], o2);
        }
        float2 oo = upk2(o2);
        float o = tanhf(oo.x + oo.y) * isq;            // premultiplied output
        out[(size_t)node * 32 + lane] = o;
        if (w4) {
            float v = o * w4l;
#pragma unroll
            for (int off = 16; off > 0; off >>= 1)
                v += __shfl_xor_sync(FULLM, v, off);
            if (lane == 0) g_hw4[node] = v;
        }
    }
}

// ---------------- layer-4 gather (scalar): x4 = tanh(isq*acc + b4) ------------
__global__ void k_gather1(const float* __restrict__ b4) {
    int node = blockIdx.x * blockDim.x + threadIdx.x;
    if (node == 0) g_zero[NN + NG] = 0;   // self-clean cursor for next replay
    if (node >= NN) return;
    int rs = g_rowstart[node];
    int re = rs + g_degc[node];
    float acc = g_hw4[node];   // self
    int e = rs;
    for (; e + 4 <= re; e += 4) {
        int s0 = __ldg(&g_esrc[e]);
        int s1 = __ldg(&g_esrc[e + 1]);
        int s2 = __ldg(&g_esrc[e + 2]);
        int s3 = __ldg(&g_esrc[e + 3]);
        acc += g_hw4[s0] + g_hw4[s1] + g_hw4[s2] + g_hw4[s3];
    }
    for (; e < re; e++) acc += g_hw4[__ldg(&g_esrc[e])];
    g_x4[node] = tanhf(acc * g_invsqrt[node] + __ldg(&b4[0]));
}

// ---------------- sort-pool + CNN/FC head ----------------
__global__ void __launch_bounds__(128) k_head(
    const float* __restrict__ w5, const float* __restrict__ b5,
    const float* __restrict__ w6, const float* __restrict__ b6,
    const float* __restrict__ fw1, const float* __restrict__ fb1,
    const float* __restrict__ fw2, const float* __restrict__ fb2,
    float* __restrict__ out) {
    const int T = 128;
    int g = blockIdx.x;
    int tid = threadIdx.x;

    __shared__ unsigned long long keys[MAXSORT];
    __shared__ float pooled[KP * CC];
    __shared__ float z5[16 * 30];
    __shared__ float p5[16 * 15];
    __shared__ float z6[352];
    __shared__ float h1[128];
    __shared__ float logits[10];
    __shared__ int   seln[KP];
    __shared__ float bestv[128];
    __shared__ int   besti[128];

    int start = g_start[g];
    int cnt   = g_cntc[g];
    int kk = cnt < KP ? cnt : KP;

    for (int i = tid; i < KP * CC; i += T) pooled[i] = 0.f;

    if (cnt <= MAXSORT) {
        int n2 = 1;
        while (n2 < cnt) n2 <<= 1;
        for (int i = tid; i < n2; i += T) {
            if (i < cnt) {
                unsigned u = __float_as_uint(g_x4[start + i]);
                u ^= (u >> 31) ? 0xFFFFFFFFu : 0x80000000u;
                u = ~u;
                keys[i] = ((unsigned long long)u << 32) | (unsigned)(start + i);
            } else {
                keys[i] = 0xFFFFFFFFFFFFFFFFull;
            }
        }
        __syncthreads();
        for (int k = 2; k <= n2; k <<= 1) {
            for (int j = k >> 1; j > 0; j >>= 1) {
                for (int i = tid; i < n2; i += T) {
                    int ixj = i ^ j;
                    if (ixj > i) {
                        bool up = ((i & k) == 0);
                        unsigned long long a = keys[i], bk = keys[ixj];
                        if ((a > bk) == up) { keys[i] = bk; keys[ixj] = a; }
                    }
                }
                __syncthreads();
            }
        }
        for (int r = tid; r < kk; r += T)
            seln[r] = (int)(keys[r] & 0xffffffffull);
        __syncthreads();
    } else {
        __shared__ float pv_s;
        __shared__ int pidx_s;
        if (tid == 0) { pv_s = 3.0e38f; pidx_s = -1; }
        __syncthreads();
        for (int r = 0; r < kk; r++) {
            float lpv = pv_s; int lpidx = pidx_s;
            float bv = -3.0e38f; int bi = 0x7fffffff;
            for (int i = start + tid; i < start + cnt; i += T) {
                float v = g_x4[i];
                bool after = (v < lpv) || (v == lpv && i > lpidx);
                if (after && ((v > bv) || (v == bv && i < bi))) { bv = v; bi = i; }
            }
            bestv[tid] = bv; besti[tid] = bi;
            __syncthreads();
            for (int sft = T / 2; sft > 0; sft >>= 1) {
                if (tid < sft) {
                    float ov = bestv[tid + sft]; int oi = besti[tid + sft];
                    if ((ov > bestv[tid]) || (ov == bestv[tid] && oi < besti[tid])) {
                        bestv[tid] = ov; besti[tid] = oi;
                    }
                }
                __syncthreads();
            }
            if (tid == 0) { seln[r] = besti[0]; pv_s = bestv[0]; pidx_s = besti[0]; }
            __syncthreads();
        }
    }

    // gather pooled rows [kk x 97] (un-premultiply with sqrtdeg)
    for (int idx = tid; idx < kk * CC; idx += T) {
        int r = idx / CC, c = idx % CC;
        int node = seln[r];
        float val;
        if (c < 96) {
            float sq = g_sqrtdeg[node];
            if (c < 32)      val = g_x1[(size_t)node * 32 + c] * sq;
            else if (c < 64) val = g_x2[(size_t)node * 32 + (c - 32)] * sq;
            else             val = g_x3[(size_t)node * 32 + (c - 64)] * sq;
        } else {
            val = g_x4[node];
        }
        pooled[r * CC + c] = val;
    }
    __syncthreads();

    for (int idx = tid; idx < 16 * 30; idx += T) {
        int oc = idx / 30, t = idx % 30;
        float s = b5[oc];
        const float* wr = &w5[oc * 97];
        const float* pr = &pooled[t * 97];
        for (int c = 0; c < 97; c++) s += pr[c] * wr[c];
        z5[oc * 30 + t] = fmaxf(s, 0.f);
    }
    __syncthreads();
    for (int idx = tid; idx < 16 * 15; idx += T) {
        int oc = idx / 15, u = idx % 15;
        p5[idx] = fmaxf(z5[oc * 30 + 2 * u], z5[oc * 30 + 2 * u + 1]);
    }
    __syncthreads();
    for (int idx = tid; idx < 352; idx += T) {
        int oc = idx / 11, v = idx % 11;
        float s = b6[oc];
        for (int ic = 0; ic < 16; ic++) {
            const float* wr = &w6[oc * 80 + ic * 5];
            const float* pr = &p5[ic * 15 + v];
#pragma unroll
            for (int qq = 0; qq < 5; qq++) s += pr[qq] * wr[qq];
        }
        z6[idx] = fmaxf(s, 0.f);
    }
    __syncthreads();
    for (int j = tid; j < 128; j += T) {
        float s = fb1[j];
        for (int i = 0; i < 352; i++) s += z6[i] * fw1[i * 128 + j];
        h1[j] = fmaxf(s, 0.f);
    }
    __syncthreads();
    for (int c = tid; c < 10; c += T) {
        float s = fb2[c];
        for (int j = 0; j < 128; j++) s += h1[j] * fw2[j * 10 + c];
        logits[c] = s;
    }
    __syncthreads();
    if (tid == 0) {
        float mx = logits[0];
        for (int c = 1; c < 10; c++) mx = fmaxf(mx, logits[c]);
        float se = 0.f;
        for (int c = 0; c < 10; c++) se += expf(logits[c] - mx);
        float lse = logf(se) + mx;
        for (int c = 0; c < 10; c++) out[(size_t)g * 10 + c] = logits[c] - lse;
    }
}

// ---------------- launch ----------------
extern "C" void kernel_launch(void* const* d_in, const int* in_sizes, int n_in,
                              void* d_out, int out_size) {
    const float* x      = (const float*)d_in[0];
    const int*   ei     = (const int*)d_in[1];
    const int*   batch  = (const int*)d_in[2];
    const float* W1 = (const float*)d_in[3];  const float* b1 = (const float*)d_in[4];
    const float* W2 = (const float*)d_in[5];  const float* b2 = (const float*)d_in[6];
    const float* W3 = (const float*)d_in[7];  const float* b3 = (const float*)d_in[8];
    const float* W4 = (const float*)d_in[9];  const float* b4 = (const float*)d_in[10];
    const float* w5 = (const float*)d_in[11]; const float* b5 = (const float*)d_in[12];
    const float* w6 = (const float*)d_in[13]; const float* b6 = (const float*)d_in[14];
    const float* fw1 = (const float*)d_in[15]; const float* fb1 = (const float*)d_in[16];
    const float* fw2 = (const float*)d_in[17]; const float* fb2 = (const float*)d_in[18];
    float* out = (float*)d_out;

    void *p_hw, *p_x1, *p_x2, *p_x3;
    cudaGetSymbolAddress(&p_hw, g_hw);
    cudaGetSymbolAddress(&p_x1, g_x1);
    cudaGetSymbolAddress(&p_x2, g_x2);
    cudaGetSymbolAddress(&p_x3, g_x3);
    float* hw = (float*)p_hw;
    float* x1 = (float*)p_x1;
    float* x2 = (float*)p_x2;
    float* x3 = (float*)p_x3;

    const int TB = 256;
    const int NB_N = NBN;
    const int NB_E4 = (NE / 4 + TB - 1) / TB;     // 3125
    const int GG_BLOCKS = 1184;                   // 8 blocks/SM * 148
    const int GG_WARPS  = GG_BLOCKS * (TB / 32);

    k_all1<<<NB_E4, TB>>>(ei, batch, x, W1, hw);
    k_prep2<<<NB_N, TB>>>(hw);
    k_fill<<<NB_E4, TB>>>(ei);
    k_gather_q<<<GG_BLOCKS, TB>>>(hw, x1, b1, GG_WARPS);
    k_gathergemm<<<GG_BLOCKS, TB>>>(x1, W2, b2, x2, nullptr, GG_WARPS);
    k_gathergemm<<<GG_BLOCKS, TB>>>(x2, W3, b3, x3, W4, GG_WARPS);
    k_gather1<<<NB_N, TB>>>(b4);
    k_head<<<NG, 128>>>(w5, b5, w6, b6, fw1, fb1, fw2, fb2, out);
}

// round 16
// speedup vs baseline: 1.1131x; 1.0783x over previous
#include <cuda_runtime.h>
#include <math.h>

#define NN 200000
#define NE 3200000
#define NG 1000
#define KP 30
#define CC 97
#define NBN 782            // ceil(NN/256)
#define MAXSORT 2048
#define FULLM 0xffffffffu

typedef unsigned long long ull;

// ---------------- device scratch ----------------
// self-cleaning atomic scratch: [0,NN) = deg, [NN,NN+NG) = graph cnt,
// [NN+NG] = rowstart cursor. Zero-init at load; each replay re-zeroes it.
__device__ int   g_zero[NN + NG + 1];
__device__ int   g_degc[NN];             // stable copy of degrees
__device__ int   g_cntc[NG];             // stable copy of graph counts
__device__ float g_invsqrt[NN];
__device__ float g_sqrtdeg[NN];
__device__ int   g_rowstart[NN];
__device__ int   g_epos[NE];             // per-edge slot within dst bucket
__device__ int   g_esrc[NE];             // CSR payload: src index only
__device__ __align__(16) float g_hw[NN * 32];   // layer-1 rows / agg scratch
__device__ __align__(16) float g_hw4[NN];
__device__ __align__(16) float g_x1[NN * 32];   // premultiplied tanh outputs
__device__ __align__(16) float g_x2[NN * 32];
__device__ __align__(16) float g_x3[NN * 32];
__device__ __align__(16) float g_x4[NN];        // raw (final layer)
__device__ int g_start[NG];

// ---------------- fp32x2 packed math ----------------
__device__ __forceinline__ ull pk2(float a, float b) {
    ull r;
    asm("mov.b64 %0, {%1, %2};" : "=l"(r) : "f"(a), "f"(b));
    return r;
}
__device__ __forceinline__ ull ffma2(ull a, ull b, ull c) {
    ull d;
    asm("fma.rn.f32x2 %0, %1, %2, %3;" : "=l"(d) : "l"(a), "l"(b), "l"(c));
    return d;
}
__device__ __forceinline__ float2 upk2(ull a) {
    float x, y;
    asm("mov.b64 {%0, %1}, %2;" : "=f"(x), "=f"(y) : "l"(a));
    return make_float2(x, y);
}

// ===== fused: edge degree atomics + per-graph counts + layer-1 GEMM (raw) =====
__global__ void __launch_bounds__(256) k_all1(
    const int* __restrict__ ei, const int* __restrict__ batch,
    const float* __restrict__ x, const float* __restrict__ W,
    float* __restrict__ hw) {
    __shared__ float sW[128 * 32];
    int tid = threadIdx.x;
    int i = blockIdx.x * 256 + tid;

    if (blockIdx.x < NBN) {
        for (int k = tid; k < 128 * 32; k += 256) sW[k] = W[k];
    }
    __syncthreads();

    int e4 = i * 4;
    int4 s, d;
    int p0 = 0, p1 = 0, p2 = 0, p3 = 0;
    bool has_edge = (e4 < NE);
    if (has_edge) {
        s = __ldg((const int4*)(ei + e4));
        d = __ldg((const int4*)(ei + NE + e4));
        if (s.x != d.x) p0 = atomicAdd(&g_zero[d.x], 1);
        if (s.y != d.y) p1 = atomicAdd(&g_zero[d.y], 1);
        if (s.z != d.z) p2 = atomicAdd(&g_zero[d.z], 1);
        if (s.w != d.w) p3 = atomicAdd(&g_zero[d.w], 1);
    }
    if (i < NN) atomicAdd(&g_zero[NN + batch[i]], 1);

    if (blockIdx.x < NBN && i < NN) {
        ull acc[16];
#pragma unroll
        for (int j = 0; j < 16; j++) acc[j] = 0ull;
        const float4* hr = (const float4*)(x + (size_t)i * 128);
#pragma unroll 4
        for (int k4 = 0; k4 < 32; k4++) {
            float4 v = hr[k4];
            const float* hk = &v.x;
#pragma unroll
            for (int kk = 0; kk < 4; kk++) {
                ull hv2 = pk2(hk[kk], hk[kk]);
                const float4* wr = (const float4*)&sW[(k4 * 4 + kk) * 32];
#pragma unroll
                for (int q = 0; q < 8; q++) {
                    float4 w = wr[q];
                    acc[2 * q]     = ffma2(hv2, pk2(w.x, w.y), acc[2 * q]);
                    acc[2 * q + 1] = ffma2(hv2, pk2(w.z, w.w), acc[2 * q + 1]);
                }
            }
        }
        float4* hwv = (float4*)(hw + (size_t)i * 32);
#pragma unroll
        for (int q = 0; q < 8; q++) {
            float2 a = upk2(acc[2 * q]);
            float2 bq = upk2(acc[2 * q + 1]);
            hwv[q] = make_float4(a.x, a.y, bq.x, bq.y);
        }
    }

    if (has_edge) *((int4*)(g_epos + e4)) = make_int4(p0, p1, p2, p3);
}

// ===== prep: read+ZERO deg/cnt, invsqrt/sqrtdeg, atomic rowstart, hw*=isq;
//       block0: graph scan into g_start + g_cntc
__global__ void __launch_bounds__(256) k_prep2(float* __restrict__ hw) {
    int tid = threadIdx.x;
    int i = blockIdx.x * 256 + tid;
    if (i < NN) {
        int dI = g_zero[i];
        g_zero[i] = 0;                    // self-clean for next replay
        g_degc[i] = dI;
        float dg = (float)dI + 1.0f;
        float is = rsqrtf(dg);
        g_invsqrt[i] = is;
        g_sqrtdeg[i] = dg * is;
        g_rowstart[i] = atomicAdd(&g_zero[NN + NG], dI);
        float4* r = (float4*)(hw + (size_t)i * 32);
#pragma unroll
        for (int q = 0; q < 8; q++) {
            float4 v = r[q];
            v.x *= is; v.y *= is; v.z *= is; v.w *= is;
            r[q] = v;
        }
    }
    if (blockIdx.x == 0) {
        __shared__ int ts[256];
        int base = tid * 4;
        int a0 = (base < NG)     ? g_zero[NN + base]     : 0;
        int a1 = (base + 1 < NG) ? g_zero[NN + base + 1] : 0;
        int a2 = (base + 2 < NG) ? g_zero[NN + base + 2] : 0;
        int a3 = (base + 3 < NG) ? g_zero[NN + base + 3] : 0;
        if (base < NG)     g_zero[NN + base]     = 0;   // self-clean
        if (base + 1 < NG) g_zero[NN + base + 1] = 0;
        if (base + 2 < NG) g_zero[NN + base + 2] = 0;
        if (base + 3 < NG) g_zero[NN + base + 3] = 0;
        int s1 = a0 + a1, s2 = s1 + a2, tot = s2 + a3;
        ts[tid] = tot;
        __syncthreads();
        for (int off = 1; off < 256; off <<= 1) {
            int v = (tid >= off) ? ts[tid - off] : 0;
            __syncthreads();
            ts[tid] += v;
            __syncthreads();
        }
        int ex = ts[tid] - tot;
        if (base < NG)     { g_start[base]     = ex;      g_cntc[base]     = a0; }
        if (base + 1 < NG) { g_start[base + 1] = ex + a0; g_cntc[base + 1] = a1; }
        if (base + 2 < NG) { g_start[base + 2] = ex + s1; g_cntc[base + 2] = a2; }
        if (base + 3 < NG) { g_start[base + 3] = ex + s2; g_cntc[base + 3] = a3; }
    }
}

// atomic-free CSR fill using recorded slots
__global__ void k_fill(const int* __restrict__ ei) {
    int i = blockIdx.x * blockDim.x + threadIdx.x;
    int e4 = i * 4;
    if (e4 >= NE) return;
    int4 s = __ldg((const int4*)(ei + e4));
    int4 d = __ldg((const int4*)(ei + NE + e4));
    int4 p = *((const int4*)(g_epos + e4));
    if (s.x != d.x) g_esrc[g_rowstart[d.x] + p.x] = s.x;
    if (s.y != d.y) g_esrc[g_rowstart[d.y] + p.y] = s.y;
    if (s.z != d.z) g_esrc[g_rowstart[d.z] + p.z] = s.z;
    if (s.w != d.w) g_esrc[g_rowstart[d.w] + p.w] = s.w;
}

// ---- 4-edge x float4 plain-sum aggregation (incl. self row), MLP=8 unroll ----
__device__ __forceinline__ float4 agg_sum(const float* __restrict__ in, int node,
                                          int g, int q) {
    int rs = g_rowstart[node];
    int re = rs + g_degc[node];      // deg
    float4 acc = __ldg((const float4*)(in + (size_t)node * 32 + q * 4)); // self
    if (g != 0) acc = make_float4(0.f, 0.f, 0.f, 0.f);
    int e = rs;
    for (; e + 8 <= re; e += 8) {
        int s0 = __ldg(&g_esrc[e + g]);
        int s1 = __ldg(&g_esrc[e + 4 + g]);
        float4 v0 = __ldg((const float4*)(in + (size_t)s0 * 32 + q * 4));
        float4 v1 = __ldg((const float4*)(in + (size_t)s1 * 32 + q * 4));
        acc.x += v0.x + v1.x; acc.y += v0.y + v1.y;
        acc.z += v0.z + v1.z; acc.w += v0.w + v1.w;
    }
    if (e + 4 <= re) {
        int s0 = __ldg(&g_esrc[e + g]);
        float4 v0 = __ldg((const float4*)(in + (size_t)s0 * 32 + q * 4));
        acc.x += v0.x; acc.y += v0.y; acc.z += v0.z; acc.w += v0.w;
        e += 4;
    }
    int rem = re - e;
    if (g < rem) {
        int s0 = __ldg(&g_esrc[e + g]);
        float4 v0 = __ldg((const float4*)(in + (size_t)s0 * 32 + q * 4));
        acc.x += v0.x; acc.y += v0.y; acc.z += v0.z; acc.w += v0.w;
    }
#pragma unroll
    for (int off = 8; off <= 16; off <<= 1) {
        acc.x += __shfl_xor_sync(FULLM, acc.x, off);
        acc.y += __shfl_xor_sync(FULLM, acc.y, off);
        acc.z += __shfl_xor_sync(FULLM, acc.z, off);
        acc.w += __shfl_xor_sync(FULLM, acc.w, off);
    }
    return acc;
}

// redistribute quad-replicated acc so lane l holds channel l
__device__ __forceinline__ float lane_channel(float4 acc, int lane) {
    int srcl = lane >> 2;
    int m = lane & 3;
    float v0 = __shfl_sync(FULLM, acc.x, srcl);
    float v1 = __shfl_sync(FULLM, acc.y, srcl);
    float v2 = __shfl_sync(FULLM, acc.z, srcl);
    float v3 = __shfl_sync(FULLM, acc.w, srcl);
    return (m == 0) ? v0 : (m == 1) ? v1 : (m == 2) ? v2 : v3;
}

// ---------------- layer-1 gather: y1 = tanh(isq*acc + b) * isq ----------------
__global__ void __launch_bounds__(256) k_gather_q(
    const float* __restrict__ in, float* __restrict__ out,
    const float* __restrict__ b, int nwarps) {
    int lane = threadIdx.x & 31;
    int wid  = (blockIdx.x * blockDim.x + threadIdx.x) >> 5;
    int g = lane >> 3, q = lane & 7;
    float bias = __ldg(&b[lane]);
    for (int node = wid; node < NN; node += nwarps) {
        float4 acc = agg_sum(in, node, g, q);
        float v = lane_channel(acc, lane);
        float isq = g_invsqrt[node];
        out[(size_t)node * 32 + lane] = tanhf(v * isq + bias) * isq;
    }
}

// ---------------- pure gather (layers 2,3): a = agg(in) * isq -----------------
__global__ void __launch_bounds__(256) k_gacc(
    const float* __restrict__ in, float* __restrict__ out, int nwarps) {
    int lane = threadIdx.x & 31;
    int wid  = (blockIdx.x * blockDim.x + threadIdx.x) >> 5;
    int g = lane >> 3, q = lane & 7;
    for (int node = wid; node < NN; node += nwarps) {
        float4 acc = agg_sum(in, node, g, q);
        float v = lane_channel(acc, lane);
        out[(size_t)node * 32 + lane] = v * g_invsqrt[node];
    }
}

// ---------- streaming row GEMM: y = tanh(a @ W + b) * isq ; optional W4 proj ---
__global__ void __launch_bounds__(256) k_rowgemm(
    const float* __restrict__ a, const float* __restrict__ W,
    const float* __restrict__ b, float* __restrict__ out,
    const float* __restrict__ w4) {
    __shared__ float sW[32 * 32];
    __shared__ float sb[32];
    __shared__ float sw4[32];
    int tid = threadIdx.x;
    for (int k = tid; k < 32 * 32; k += 256) sW[k] = W[k];
    if (tid < 32) {
        sb[tid] = b[tid];
        sw4[tid] = w4 ? w4[tid] : 0.f;
    }
    __syncthreads();
    int node = blockIdx.x * 256 + tid;
    if (node >= NN) return;
    ull acc[16];
#pragma unroll
    for (int j = 0; j < 16; j++) acc[j] = 0ull;
    const float4* ar = (const float4*)(a + (size_t)node * 32);
#pragma unroll 2
    for (int k4 = 0; k4 < 8; k4++) {
        float4 v = ar[k4];
        const float* hk = &v.x;
#pragma unroll
        for (int kk = 0; kk < 4; kk++) {
            ull hv2 = pk2(hk[kk], hk[kk]);
            const float4* wr = (const float4*)&sW[(k4 * 4 + kk) * 32];
#pragma unroll
            for (int q = 0; q < 8; q++) {
                float4 w = wr[q];
                acc[2 * q]     = ffma2(hv2, pk2(w.x, w.y), acc[2 * q]);
                acc[2 * q + 1] = ffma2(hv2, pk2(w.z, w.w), acc[2 * q + 1]);
            }
        }
    }
    float isq = g_invsqrt[node];
    float4* ov = (float4*)(out + (size_t)node * 32);
    float h4 = 0.f;
#pragma unroll
    for (int q = 0; q < 8; q++) {
        float2 aa = upk2(acc[2 * q]);
        float2 bb = upk2(acc[2 * q + 1]);
        float4 o;
        o.x = tanhf(aa.x + sb[4 * q])     * isq;
        o.y = tanhf(aa.y + sb[4 * q + 1]) * isq;
        o.z = tanhf(bb.x + sb[4 * q + 2]) * isq;
        o.w = tanhf(bb.y + sb[4 * q + 3]) * isq;
        ov[q] = o;
        h4 += o.x * sw4[4 * q] + o.y * sw4[4 * q + 1]
            + o.z * sw4[4 * q + 2] + o.w * sw4[4 * q + 3];
    }
    if (w4) g_hw4[node] = h4;
}

// ---------------- layer-4 gather (scalar): x4 = tanh(isq*acc + b4) ------------
__global__ void k_gather1(const float* __restrict__ b4) {
    int node = blockIdx.x * blockDim.x + threadIdx.x;
    if (node == 0) g_zero[NN + NG] = 0;   // self-clean cursor for next replay
    if (node >= NN) return;
    int rs = g_rowstart[node];
    int re = rs + g_degc[node];
    float acc = g_hw4[node];   // self
    int e = rs;
    for (; e + 4 <= re; e += 4) {
        int s0 = __ldg(&g_esrc[e]);
        int s1 = __ldg(&g_esrc[e + 1]);
        int s2 = __ldg(&g_esrc[e + 2]);
        int s3 = __ldg(&g_esrc[e + 3]);
        acc += g_hw4[s0] + g_hw4[s1] + g_hw4[s2] + g_hw4[s3];
    }
    for (; e < re; e++) acc += g_hw4[__ldg(&g_esrc[e])];
    g_x4[node] = tanhf(acc * g_invsqrt[node] + __ldg(&b4[0]));
}

// ---------------- sort-pool + CNN/FC head ----------------
__global__ void __launch_bounds__(128) k_head(
    const float* __restrict__ w5, const float* __restrict__ b5,
    const float* __restrict__ w6, const float* __restrict__ b6,
    const float* __restrict__ fw1, const float* __restrict__ fb1,
    const float* __restrict__ fw2, const float* __restrict__ fb2,
    float* __restrict__ out) {
    const int T = 128;
    int g = blockIdx.x;
    int tid = threadIdx.x;

    __shared__ unsigned long long keys[MAXSORT];
    __shared__ float pooled[KP * CC];
    __shared__ float z5[16 * 30];
    __shared__ float p5[16 * 15];
    __shared__ float z6[352];
    __shared__ float h1[128];
    __shared__ float logits[10];
    __shared__ int   seln[KP];
    __shared__ float bestv[128];
    __shared__ int   besti[128];

    int start = g_start[g];
    int cnt   = g_cntc[g];
    int kk = cnt < KP ? cnt : KP;

    for (int i = tid; i < KP * CC; i += T) pooled[i] = 0.f;

    if (cnt <= MAXSORT) {
        int n2 = 1;
        while (n2 < cnt) n2 <<= 1;
        for (int i = tid; i < n2; i += T) {
            if (i < cnt) {
                unsigned u = __float_as_uint(g_x4[start + i]);
                u ^= (u >> 31) ? 0xFFFFFFFFu : 0x80000000u;
                u = ~u;
                keys[i] = ((unsigned long long)u << 32) | (unsigned)(start + i);
            } else {
                keys[i] = 0xFFFFFFFFFFFFFFFFull;
            }
        }
        __syncthreads();
        for (int k = 2; k <= n2; k <<= 1) {
            for (int j = k >> 1; j > 0; j >>= 1) {
                for (int i = tid; i < n2; i += T) {
                    int ixj = i ^ j;
                    if (ixj > i) {
                        bool up = ((i & k) == 0);
                        unsigned long long a = keys[i], bk = keys[ixj];
                        if ((a > bk) == up) { keys[i] = bk; keys[ixj] = a; }
                    }
                }
                __syncthreads();
            }
        }
        for (int r = tid; r < kk; r += T)
            seln[r] = (int)(keys[r] & 0xffffffffull);
        __syncthreads();
    } else {
        __shared__ float pv_s;
        __shared__ int pidx_s;
        if (tid == 0) { pv_s = 3.0e38f; pidx_s = -1; }
        __syncthreads();
        for (int r = 0; r < kk; r++) {
            float lpv = pv_s; int lpidx = pidx_s;
            float bv = -3.0e38f; int bi = 0x7fffffff;
            for (int i = start + tid; i < start + cnt; i += T) {
                float v = g_x4[i];
                bool after = (v < lpv) || (v == lpv && i > lpidx);
                if (after && ((v > bv) || (v == bv && i < bi))) { bv = v; bi = i; }
            }
            bestv[tid] = bv; besti[tid] = bi;
            __syncthreads();
            for (int sft = T / 2; sft > 0; sft >>= 1) {
                if (tid < sft) {
                    float ov = bestv[tid + sft]; int oi = besti[tid + sft];
                    if ((ov > bestv[tid]) || (ov == bestv[tid] && oi < besti[tid])) {
                        bestv[tid] = ov; besti[tid] = oi;
                    }
                }
                __syncthreads();
            }
            if (tid == 0) { seln[r] = besti[0]; pv_s = bestv[0]; pidx_s = besti[0]; }
            __syncthreads();
        }
    }

    // gather pooled rows [kk x 97] (un-premultiply with sqrtdeg)
    for (int idx = tid; idx < kk * CC; idx += T) {
        int r = idx / CC, c = idx % CC;
        int node = seln[r];
        float val;
        if (c < 96) {
            float sq = g_sqrtdeg[node];
            if (c < 32)      val = g_x1[(size_t)node * 32 + c] * sq;
            else if (c < 64) val = g_x2[(size_t)node * 32 + (c - 32)] * sq;
            else             val = g_x3[(size_t)node * 32 + (c - 64)] * sq;
        } else {
            val = g_x4[node];
        }
        pooled[r * CC + c] = val;
    }
    __syncthreads();

    for (int idx = tid; idx < 16 * 30; idx += T) {
        int oc = idx / 30, t = idx % 30;
        float s = b5[oc];
        const float* wr = &w5[oc * 97];
        const float* pr = &pooled[t * 97];
        for (int c = 0; c < 97; c++) s += pr[c] * wr[c];
        z5[oc * 30 + t] = fmaxf(s, 0.f);
    }
    __syncthreads();
    for (int idx = tid; idx < 16 * 15; idx += T) {
        int oc = idx / 15, u = idx % 15;
        p5[idx] = fmaxf(z5[oc * 30 + 2 * u], z5[oc * 30 + 2 * u + 1]);
    }
    __syncthreads();
    for (int idx = tid; idx < 352; idx += T) {
        int oc = idx / 11, v = idx % 11;
        float s = b6[oc];
        for (int ic = 0; ic < 16; ic++) {
            const float* wr = &w6[oc * 80 + ic * 5];
            const float* pr = &p5[ic * 15 + v];
#pragma unroll
            for (int qq = 0; qq < 5; qq++) s += pr[qq] * wr[qq];
        }
        z6[idx] = fmaxf(s, 0.f);
    }
    __syncthreads();
    for (int j = tid; j < 128; j += T) {
        float s = fb1[j];
        for (int i = 0; i < 352; i++) s += z6[i] * fw1[i * 128 + j];
        h1[j] = fmaxf(s, 0.f);
    }
    __syncthreads();
    for (int c = tid; c < 10; c += T) {
        float s = fb2[c];
        for (int j = 0; j < 128; j++) s += h1[j] * fw2[j * 10 + c];
        logits[c] = s;
    }
    __syncthreads();
    if (tid == 0) {
        float mx = logits[0];
        for (int c = 1; c < 10; c++) mx = fmaxf(mx, logits[c]);
        float se = 0.f;
        for (int c = 0; c < 10; c++) se += expf(logits[c] - mx);
        float lse = logf(se) + mx;
        for (int c = 0; c < 10; c++) out[(size_t)g * 10 + c] = logits[c] - lse;
    }
}

// ---------------- launch ----------------
extern "C" void kernel_launch(void* const* d_in, const int* in_sizes, int n_in,
                              void* d_out, int out_size) {
    const float* x      = (const float*)d_in[0];
    const int*   ei     = (const int*)d_in[1];
    const int*   batch  = (const int*)d_in[2];
    const float* W1 = (const float*)d_in[3];  const float* b1 = (const float*)d_in[4];
    const float* W2 = (const float*)d_in[5];  const float* b2 = (const float*)d_in[6];
    const float* W3 = (const float*)d_in[7];  const float* b3 = (const float*)d_in[8];
    const float* W4 = (const float*)d_in[9];  const float* b4 = (const float*)d_in[10];
    const float* w5 = (const float*)d_in[11]; const float* b5 = (const float*)d_in[12];
    const float* w6 = (const float*)d_in[13]; const float* b6 = (const float*)d_in[14];
    const float* fw1 = (const float*)d_in[15]; const float* fb1 = (const float*)d_in[16];
    const float* fw2 = (const float*)d_in[17]; const float* fb2 = (const float*)d_in[18];
    float* out = (float*)d_out;

    void *p_hw, *p_x1, *p_x2, *p_x3;
    cudaGetSymbolAddress(&p_hw, g_hw);
    cudaGetSymbolAddress(&p_x1, g_x1);
    cudaGetSymbolAddress(&p_x2, g_x2);
    cudaGetSymbolAddress(&p_x3, g_x3);
    float* hw = (float*)p_hw;
    float* x1 = (float*)p_x1;
    float* x2 = (float*)p_x2;
    float* x3 = (float*)p_x3;

    const int TB = 256;
    const int NB_N = NBN;
    const int NB_E4 = (NE / 4 + TB - 1) / TB;     // 3125
    const int GG_BLOCKS = 1184;                   // 8 blocks/SM * 148
    const int GG_WARPS  = GG_BLOCKS * (TB / 32);

    k_all1<<<NB_E4, TB>>>(ei, batch, x, W1, hw);
    k_prep2<<<NB_N, TB>>>(hw);
    k_fill<<<NB_E4, TB>>>(ei);
    // layer 1
    k_gather_q<<<GG_BLOCKS, TB>>>(hw, x1, b1, GG_WARPS);
    // layer 2: pure gather then streaming GEMM
    k_gacc<<<GG_BLOCKS, TB>>>(x1, hw, GG_WARPS);
    k_rowgemm<<<NB_N, TB>>>(hw, W2, b2, x2, nullptr);
    // layer 3: same, plus fused W4 projection
    k_gacc<<<GG_BLOCKS, TB>>>(x2, hw, GG_WARPS);
    k_rowgemm<<<NB_N, TB>>>(hw, W3, b3, x3, W4);
    // layer 4
    k_gather1<<<NB_N, TB>>>(b4);
    k_head<<<NG, 128>>>(w5, b5, w6, b6, fw1, fb1, fw2, fb2, out);
}

// round 17
// speedup vs baseline: 1.1283x; 1.0136x over previous
#include <cuda_runtime.h>
#include <math.h>

#define NN 200000
#define NE 3200000
#define NG 1000
#define KP 30
#define CC 97
#define NBN 782            // ceil(NN/256)
#define MAXSORT 2048
#define FULLM 0xffffffffu

typedef unsigned long long ull;

// ---------------- device scratch ----------------
__device__ int   g_zero[NN + NG + 1];   // self-cleaning: deg | cnt | cursor
__device__ int   g_degc[NN];
__device__ int   g_cntc[NG];
__device__ float g_invsqrt[NN];
__device__ float g_sqrtdeg[NN];
__device__ int   g_rowstart[NN];
__device__ int   g_epos[NE];
__device__ int   g_esrc[NE];
__device__ __align__(16) float g_hw[NN * 32];
__device__ __align__(16) float g_hw4[NN];
__device__ __align__(16) float g_x1[NN * 32];
__device__ __align__(16) float g_x2[NN * 32];
__device__ __align__(16) float g_x3[NN * 32];
__device__ __align__(16) float g_x4[NN];
__device__ int g_start[NG];

// ---------------- fp32x2 packed math ----------------
__device__ __forceinline__ ull pk2(float a, float b) {
    ull r;
    asm("mov.b64 %0, {%1, %2};" : "=l"(r) : "f"(a), "f"(b));
    return r;
}
__device__ __forceinline__ ull ffma2(ull a, ull b, ull c) {
    ull d;
    asm("fma.rn.f32x2 %0, %1, %2, %3;" : "=l"(d) : "l"(a), "l"(b), "l"(c));
    return d;
}
__device__ __forceinline__ float2 upk2(ull a) {
    float x, y;
    asm("mov.b64 {%0, %1}, %2;" : "=f"(x), "=f"(y) : "l"(a));
    return make_float2(x, y);
}

// ===== fused: edge degree atomics + per-graph counts + layer-1 GEMM (raw) =====
__global__ void __launch_bounds__(256) k_all1(
    const int* __restrict__ ei, const int* __restrict__ batch,
    const float* __restrict__ x, const float* __restrict__ W,
    float* __restrict__ hw) {
    __shared__ float sW[128 * 32];
    int tid = threadIdx.x;
    int i = blockIdx.x * 256 + tid;

    if (blockIdx.x < NBN) {
        for (int k = tid; k < 128 * 32; k += 256) sW[k] = W[k];
    }
    __syncthreads();

    int e4 = i * 4;
    int4 s, d;
    int p0 = 0, p1 = 0, p2 = 0, p3 = 0;
    bool has_edge = (e4 < NE);
    if (has_edge) {
        s = __ldg((const int4*)(ei + e4));
        d = __ldg((const int4*)(ei + NE + e4));
        if (s.x != d.x) p0 = atomicAdd(&g_zero[d.x], 1);
        if (s.y != d.y) p1 = atomicAdd(&g_zero[d.y], 1);
        if (s.z != d.z) p2 = atomicAdd(&g_zero[d.z], 1);
        if (s.w != d.w) p3 = atomicAdd(&g_zero[d.w], 1);
    }
    if (i < NN) atomicAdd(&g_zero[NN + batch[i]], 1);

    if (blockIdx.x < NBN && i < NN) {
        ull acc[16];
#pragma unroll
        for (int j = 0; j < 16; j++) acc[j] = 0ull;
        const float4* hr = (const float4*)(x + (size_t)i * 128);
#pragma unroll 4
        for (int k4 = 0; k4 < 32; k4++) {
            float4 v = hr[k4];
            const float* hk = &v.x;
#pragma unroll
            for (int kk = 0; kk < 4; kk++) {
                ull hv2 = pk2(hk[kk], hk[kk]);
                const float4* wr = (const float4*)&sW[(k4 * 4 + kk) * 32];
#pragma unroll
                for (int q = 0; q < 8; q++) {
                    float4 w = wr[q];
                    acc[2 * q]     = ffma2(hv2, pk2(w.x, w.y), acc[2 * q]);
                    acc[2 * q + 1] = ffma2(hv2, pk2(w.z, w.w), acc[2 * q + 1]);
                }
            }
        }
        float4* hwv = (float4*)(hw + (size_t)i * 32);
#pragma unroll
        for (int q = 0; q < 8; q++) {
            float2 a = upk2(acc[2 * q]);
            float2 bq = upk2(acc[2 * q + 1]);
            hwv[q] = make_float4(a.x, a.y, bq.x, bq.y);
        }
    }

    if (has_edge) *((int4*)(g_epos + e4)) = make_int4(p0, p1, p2, p3);
}

// ===== prep =====
__global__ void __launch_bounds__(256) k_prep2(float* __restrict__ hw) {
    int tid = threadIdx.x;
    int i = blockIdx.x * 256 + tid;
    if (i < NN) {
        int dI = g_zero[i];
        g_zero[i] = 0;
        g_degc[i] = dI;
        float dg = (float)dI + 1.0f;
        float is = rsqrtf(dg);
        g_invsqrt[i] = is;
        g_sqrtdeg[i] = dg * is;
        g_rowstart[i] = atomicAdd(&g_zero[NN + NG], dI);
        float4* r = (float4*)(hw + (size_t)i * 32);
#pragma unroll
        for (int q = 0; q < 8; q++) {
            float4 v = r[q];
            v.x *= is; v.y *= is; v.z *= is; v.w *= is;
            r[q] = v;
        }
    }
    if (blockIdx.x == 0) {
        __shared__ int ts[256];
        int base = tid * 4;
        int a0 = (base < NG)     ? g_zero[NN + base]     : 0;
        int a1 = (base + 1 < NG) ? g_zero[NN + base + 1] : 0;
        int a2 = (base + 2 < NG) ? g_zero[NN + base + 2] : 0;
        int a3 = (base + 3 < NG) ? g_zero[NN + base + 3] : 0;
        if (base < NG)     g_zero[NN + base]     = 0;
        if (base + 1 < NG) g_zero[NN + base + 1] = 0;
        if (base + 2 < NG) g_zero[NN + base + 2] = 0;
        if (base + 3 < NG) g_zero[NN + base + 3] = 0;
        int s1 = a0 + a1, s2 = s1 + a2, tot = s2 + a3;
        ts[tid] = tot;
        __syncthreads();
        for (int off = 1; off < 256; off <<= 1) {
            int v = (tid >= off) ? ts[tid - off] : 0;
            __syncthreads();
            ts[tid] += v;
            __syncthreads();
        }
        int ex = ts[tid] - tot;
        if (base < NG)     { g_start[base]     = ex;      g_cntc[base]     = a0; }
        if (base + 1 < NG) { g_start[base + 1] = ex + a0; g_cntc[base + 1] = a1; }
        if (base + 2 < NG) { g_start[base + 2] = ex + s1; g_cntc[base + 2] = a2; }
        if (base + 3 < NG) { g_start[base + 3] = ex + s2; g_cntc[base + 3] = a3; }
    }
}

// atomic-free CSR fill using recorded slots
__global__ void k_fill(const int* __restrict__ ei) {
    int i = blockIdx.x * blockDim.x + threadIdx.x;
    int e4 = i * 4;
    if (e4 >= NE) return;
    int4 s = __ldg((const int4*)(ei + e4));
    int4 d = __ldg((const int4*)(ei + NE + e4));
    int4 p = *((const int4*)(g_epos + e4));
    if (s.x != d.x) g_esrc[g_rowstart[d.x] + p.x] = s.x;
    if (s.y != d.y) g_esrc[g_rowstart[d.y] + p.y] = s.y;
    if (s.z != d.z) g_esrc[g_rowstart[d.z] + p.z] = s.z;
    if (s.w != d.w) g_esrc[g_rowstart[d.w] + p.w] = s.w;
}

// ---- 2-node-per-warp aggregation: lane = h*16 + g*8 + q ----------------------
// Per node: 2 edge groups, 4 edges per iteration (2 loads/group). After the
// xor-8 reduce, all 16 lanes of half h hold node h's full quad set.
__device__ __forceinline__ float4 agg2(const float* __restrict__ in, int node,
                                       int g, int q) {
    int rs = g_rowstart[node];
    int re = rs + g_degc[node];
    float4 acc = __ldg((const float4*)(in + (size_t)node * 32 + q * 4)); // self
    if (g != 0) acc = make_float4(0.f, 0.f, 0.f, 0.f);
    int e = rs;
    for (; e + 4 <= re; e += 4) {
        int s0 = __ldg(&g_esrc[e + g]);
        int s1 = __ldg(&g_esrc[e + 2 + g]);
        float4 v0 = __ldg((const float4*)(in + (size_t)s0 * 32 + q * 4));
        float4 v1 = __ldg((const float4*)(in + (size_t)s1 * 32 + q * 4));
        acc.x += v0.x + v1.x; acc.y += v0.y + v1.y;
        acc.z += v0.z + v1.z; acc.w += v0.w + v1.w;
    }
    if (e + 2 <= re) {
        int s0 = __ldg(&g_esrc[e + g]);
        float4 v0 = __ldg((const float4*)(in + (size_t)s0 * 32 + q * 4));
        acc.x += v0.x; acc.y += v0.y; acc.z += v0.z; acc.w += v0.w;
        e += 2;
    }
    if (g < re - e) {
        int s0 = __ldg(&g_esrc[e + g]);
        float4 v0 = __ldg((const float4*)(in + (size_t)s0 * 32 + q * 4));
        acc.x += v0.x; acc.y += v0.y; acc.z += v0.z; acc.w += v0.w;
    }
    // reduce across the 2 edge groups (stay within the 16-lane half)
    acc.x += __shfl_xor_sync(FULLM, acc.x, 8);
    acc.y += __shfl_xor_sync(FULLM, acc.y, 8);
    acc.z += __shfl_xor_sync(FULLM, acc.z, 8);
    acc.w += __shfl_xor_sync(FULLM, acc.w, 8);
    return acc;
}

// ---------------- layer-1 gather: y1 = tanh(isq*acc + b) * isq ----------------
// 2 nodes/warp; epilogue redistributes to 2 channels per lane (full-warp tanh).
__global__ void __launch_bounds__(256) k_gather_q(
    const float* __restrict__ in, float* __restrict__ out,
    const float* __restrict__ b, int nwarps) {
    int lane = threadIdx.x & 31;
    int wid  = (blockIdx.x * blockDim.x + threadIdx.x) >> 5;
    int h = lane >> 4, g = (lane >> 3) & 1, q = lane & 7;
    int l16 = lane & 15;
    float2 bias2 = __ldg(((const float2*)b) + l16);   // channels 2*l16, 2*l16+1
    int src = (h << 4) + (l16 >> 1);
    for (int pair = wid; pair < NN / 2; pair += nwarps) {
        int node = 2 * pair + h;
        float4 acc = agg2(in, node, g, q);
        float a0 = __shfl_sync(FULLM, acc.x, src);
        float a1 = __shfl_sync(FULLM, acc.y, src);
        float a2 = __shfl_sync(FULLM, acc.z, src);
        float a3 = __shfl_sync(FULLM, acc.w, src);
        float u0 = (lane & 1) ? a2 : a0;
        float u1 = (lane & 1) ? a3 : a1;
        float isq = g_invsqrt[node];
        float2 o;
        o.x = tanhf(u0 * isq + bias2.x) * isq;
        o.y = tanhf(u1 * isq + bias2.y) * isq;
        ((float2*)(out + (size_t)node * 32))[l16] = o;
    }
}

// ---------------- pure gather (layers 2,3): a = agg(in) * isq -----------------
__global__ void __launch_bounds__(256) k_gacc(
    const float* __restrict__ in, float* __restrict__ out, int nwarps) {
    int lane = threadIdx.x & 31;
    int wid  = (blockIdx.x * blockDim.x + threadIdx.x) >> 5;
    int h = lane >> 4, g = (lane >> 3) & 1, q = lane & 7;
    for (int pair = wid; pair < NN / 2; pair += nwarps) {
        int node = 2 * pair + h;
        float4 acc = agg2(in, node, g, q);
        if (g == 0) {
            float isq = g_invsqrt[node];
            float4 o;
            o.x = acc.x * isq; o.y = acc.y * isq;
            o.z = acc.z * isq; o.w = acc.w * isq;
            *((float4*)(out + (size_t)node * 32 + q * 4)) = o;
        }
    }
}

// ---------- streaming row GEMM: y = tanh(a @ W + b) * isq ; optional W4 proj ---
__global__ void __launch_bounds__(256) k_rowgemm(
    const float* __restrict__ a, const float* __restrict__ W,
    const float* __restrict__ b, float* __restrict__ out,
    const float* __restrict__ w4) {
    __shared__ float sW[32 * 32];
    __shared__ float sb[32];
    __shared__ float sw4[32];
    int tid = threadIdx.x;
    for (int k = tid; k < 32 * 32; k += 256) sW[k] = W[k];
    if (tid < 32) {
        sb[tid] = b[tid];
        sw4[tid] = w4 ? w4[tid] : 0.f;
    }
    __syncthreads();
    int node = blockIdx.x * 256 + tid;
    if (node >= NN) return;
    ull acc[16];
#pragma unroll
    for (int j = 0; j < 16; j++) acc[j] = 0ull;
    const float4* ar = (const float4*)(a + (size_t)node * 32);
#pragma unroll 2
    for (int k4 = 0; k4 < 8; k4++) {
        float4 v = ar[k4];
        const float* hk = &v.x;
#pragma unroll
        for (int kk = 0; kk < 4; kk++) {
            ull hv2 = pk2(hk[kk], hk[kk]);
            const float4* wr = (const float4*)&sW[(k4 * 4 + kk) * 32];
#pragma unroll
            for (int q = 0; q < 8; q++) {
                float4 w = wr[q];
                acc[2 * q]     = ffma2(hv2, pk2(w.x, w.y), acc[2 * q]);
                acc[2 * q + 1] = ffma2(hv2, pk2(w.z, w.w), acc[2 * q + 1]);
            }
        }
    }
    float isq = g_invsqrt[node];
    float4* ov = (float4*)(out + (size_t)node * 32);
    float h4 = 0.f;
#pragma unroll
    for (int q = 0; q < 8; q++) {
        float2 aa = upk2(acc[2 * q]);
        float2 bb = upk2(acc[2 * q + 1]);
        float4 o;
        o.x = tanhf(aa.x + sb[4 * q])     * isq;
        o.y = tanhf(aa.y + sb[4 * q + 1]) * isq;
        o.z = tanhf(bb.x + sb[4 * q + 2]) * isq;
        o.w = tanhf(bb.y + sb[4 * q + 3]) * isq;
        ov[q] = o;
        h4 += o.x * sw4[4 * q] + o.y * sw4[4 * q + 1]
            + o.z * sw4[4 * q + 2] + o.w * sw4[4 * q + 3];
    }
    if (w4) g_hw4[node] = h4;
}

// ---------------- layer-4 gather (scalar): x4 = tanh(isq*acc + b4) ------------
__global__ void k_gather1(const float* __restrict__ b4) {
    int node = blockIdx.x * blockDim.x + threadIdx.x;
    if (node == 0) g_zero[NN + NG] = 0;
    if (node >= NN) return;
    int rs = g_rowstart[node];
    int re = rs + g_degc[node];
    float acc = g_hw4[node];
    int e = rs;
    for (; e + 4 <= re; e += 4) {
        int s0 = __ldg(&g_esrc[e]);
        int s1 = __ldg(&g_esrc[e + 1]);
        int s2 = __ldg(&g_esrc[e + 2]);
        int s3 = __ldg(&g_esrc[e + 3]);
        acc += g_hw4[s0] + g_hw4[s1] + g_hw4[s2] + g_hw4[s3];
    }
    for (; e < re; e++) acc += g_hw4[__ldg(&g_esrc[e])];
    g_x4[node] = tanhf(acc * g_invsqrt[node] + __ldg(&b4[0]));
}

// ---------------- sort-pool + CNN/FC head ----------------
__global__ void __launch_bounds__(128) k_head(
    const float* __restrict__ w5, const float* __restrict__ b5,
    const float* __restrict__ w6, const float* __restrict__ b6,
    const float* __restrict__ fw1, const float* __restrict__ fb1,
    const float* __restrict__ fw2, const float* __restrict__ fb2,
    float* __restrict__ out) {
    const int T = 128;
    int g = blockIdx.x;
    int tid = threadIdx.x;

    __shared__ unsigned long long keys[MAXSORT];
    __shared__ float pooled[KP * CC];
    __shared__ float z5[16 * 30];
    __shared__ float p5[16 * 15];
    __shared__ float z6[352];
    __shared__ float h1[128];
    __shared__ float logits[10];
    __shared__ int   seln[KP];
    __shared__ float bestv[128];
    __shared__ int   besti[128];

    int start = g_start[g];
    int cnt   = g_cntc[g];
    int kk = cnt < KP ? cnt : KP;

    for (int i = tid; i < KP * CC; i += T) pooled[i] = 0.f;

    if (cnt <= MAXSORT) {
        int n2 = 1;
        while (n2 < cnt) n2 <<= 1;
        for (int i = tid; i < n2; i += T) {
            if (i < cnt) {
                unsigned u = __float_as_uint(g_x4[start + i]);
                u ^= (u >> 31) ? 0xFFFFFFFFu : 0x80000000u;
                u = ~u;
                keys[i] = ((unsigned long long)u << 32) | (unsigned)(start + i);
            } else {
                keys[i] = 0xFFFFFFFFFFFFFFFFull;
            }
        }
        __syncthreads();
        for (int k = 2; k <= n2; k <<= 1) {
            for (int j = k >> 1; j > 0; j >>= 1) {
                for (int i = tid; i < n2; i += T) {
                    int ixj = i ^ j;
                    if (ixj > i) {
                        bool up = ((i & k) == 0);
                        unsigned long long a = keys[i], bk = keys[ixj];
                        if ((a > bk) == up) { keys[i] = bk; keys[ixj] = a; }
                    }
                }
                __syncthreads();
            }
        }
        for (int r = tid; r < kk; r += T)
            seln[r] = (int)(keys[r] & 0xffffffffull);
        __syncthreads();
    } else {
        __shared__ float pv_s;
        __shared__ int pidx_s;
        if (tid == 0) { pv_s = 3.0e38f; pidx_s = -1; }
        __syncthreads();
        for (int r = 0; r < kk; r++) {
            float lpv = pv_s; int lpidx = pidx_s;
            float bv = -3.0e38f; int bi = 0x7fffffff;
            for (int i = start + tid; i < start + cnt; i += T) {
                float v = g_x4[i];
                bool after = (v < lpv) || (v == lpv && i > lpidx);
                if (after && ((v > bv) || (v == bv && i < bi))) { bv = v; bi = i; }
            }
            bestv[tid] = bv; besti[tid] = bi;
            __syncthreads();
            for (int sft = T / 2; sft > 0; sft >>= 1) {
                if (tid < sft) {
                    float ov = bestv[tid + sft]; int oi = besti[tid + sft];
                    if ((ov > bestv[tid]) || (ov == bestv[tid] && oi < besti[tid])) {
                        bestv[tid] = ov; besti[tid] = oi;
                    }
                }
                __syncthreads();
            }
            if (tid == 0) { seln[r] = besti[0]; pv_s = bestv[0]; pidx_s = besti[0]; }
            __syncthreads();
        }
    }

    // gather pooled rows [kk x 97] (un-premultiply with sqrtdeg)
    for (int idx = tid; idx < kk * CC; idx += T) {
        int r = idx / CC, c = idx % CC;
        int node = seln[r];
        float val;
        if (c < 96) {
            float sq = g_sqrtdeg[node];
            if (c < 32)      val = g_x1[(size_t)node * 32 + c] * sq;
            else if (c < 64) val = g_x2[(size_t)node * 32 + (c - 32)] * sq;
            else             val = g_x3[(size_t)node * 32 + (c - 64)] * sq;
        } else {
            val = g_x4[node];
        }
        pooled[r * CC + c] = val;
    }
    __syncthreads();

    for (int idx = tid; idx < 16 * 30; idx += T) {
        int oc = idx / 30, t = idx % 30;
        float s = b5[oc];
        const float* wr = &w5[oc * 97];
        const float* pr = &pooled[t * 97];
        for (int c = 0; c < 97; c++) s += pr[c] * wr[c];
        z5[oc * 30 + t] = fmaxf(s, 0.f);
    }
    __syncthreads();
    for (int idx = tid; idx < 16 * 15; idx += T) {
        int oc = idx / 15, u = idx % 15;
        p5[idx] = fmaxf(z5[oc * 30 + 2 * u], z5[oc * 30 + 2 * u + 1]);
    }
    __syncthreads();
    for (int idx = tid; idx < 352; idx += T) {
        int oc = idx / 11, v = idx % 11;
        float s = b6[oc];
        for (int ic = 0; ic < 16; ic++) {
            const float* wr = &w6[oc * 80 + ic * 5];
            const float* pr = &p5[ic * 15 + v];
#pragma unroll
            for (int qq = 0; qq < 5; qq++) s += pr[qq] * wr[qq];
        }
        z6[idx] = fmaxf(s, 0.f);
    }
    __syncthreads();
    for (int j = tid; j < 128; j += T) {
        float s = fb1[j];
        for (int i = 0; i < 352; i++) s += z6[i] * fw1[i * 128 + j];
        h1[j] = fmaxf(s, 0.f);
    }
    __syncthreads();
    for (int c = tid; c < 10; c += T) {
        float s = fb2[c];
        for (int j = 0; j < 128; j++) s += h1[j] * fw2[j * 10 + c];
        logits[c] = s;
    }
    __syncthreads();
    if (tid == 0) {
        float mx = logits[0];
        for (int c = 1; c < 10; c++) mx = fmaxf(mx, logits[c]);
        float se = 0.f;
        for (int c = 0; c < 10; c++) se += expf(logits[c] - mx);
        float lse = logf(se) + mx;
        for (int c = 0; c < 10; c++) out[(size_t)g * 10 + c] = logits[c] - lse;
    }
}

// ---------------- launch ----------------
extern "C" void kernel_launch(void* const* d_in, const int* in_sizes, int n_in,
                              void* d_out, int out_size) {
    const float* x      = (const float*)d_in[0];
    const int*   ei     = (const int*)d_in[1];
    const int*   batch  = (const int*)d_in[2];
    const float* W1 = (const float*)d_in[3];  const float* b1 = (const float*)d_in[4];
    const float* W2 = (const float*)d_in[5];  const float* b2 = (const float*)d_in[6];
    const float* W3 = (const float*)d_in[7];  const float* b3 = (const float*)d_in[8];
    const float* W4 = (const float*)d_in[9];  const float* b4 = (const float*)d_in[10];
    const float* w5 = (const float*)d_in[11]; const float* b5 = (const float*)d_in[12];
    const float* w6 = (const float*)d_in[13]; const float* b6 = (const float*)d_in[14];
    const float* fw1 = (const float*)d_in[15]; const float* fb1 = (const float*)d_in[16];
    const float* fw2 = (const float*)d_in[17]; const float* fb2 = (const float*)d_in[18];
    float* out = (float*)d_out;

    void *p_hw, *p_x1, *p_x2, *p_x3;
    cudaGetSymbolAddress(&p_hw, g_hw);
    cudaGetSymbolAddress(&p_x1, g_x1);
    cudaGetSymbolAddress(&p_x2, g_x2);
    cudaGetSymbolAddress(&p_x3, g_x3);
    float* hw = (float*)p_hw;
    float* x1 = (float*)p_x1;
    float* x2 = (float*)p_x2;
    float* x3 = (float*)p_x3;

    const int TB = 256;
    const int NB_N = NBN;
    const int NB_E4 = (NE / 4 + TB - 1) / TB;     // 3125
    const int GG_BLOCKS = 1184;                   // 8 blocks/SM * 148
    const int GG_WARPS  = GG_BLOCKS * (TB / 32);

    k_all1<<<NB_E4, TB>>>(ei, batch, x, W1, hw);
    k_prep2<<<NB_N, TB>>>(hw);
    k_fill<<<NB_E4, TB>>>(ei);
    // layer 1
    k_gather_q<<<GG_BLOCKS, TB>>>(hw, x1, b1, GG_WARPS);
    // layer 2: pure gather then streaming GEMM
    k_gacc<<<GG_BLOCKS, TB>>>(x1, hw, GG_WARPS);
    k_rowgemm<<<NB_N, TB>>>(hw, W2, b2, x2, nullptr);
    // layer 3: same, plus fused W4 projection
    k_gacc<<<GG_BLOCKS, TB>>>(x2, hw, GG_WARPS);
    k_rowgemm<<<NB_N, TB>>>(hw, W3, b3, x3, W4);
    // layer 4
    k_gather1<<<NB_N, TB>>>(b4);
    k_head<<<NG, 128>>>(w5, b5, w6, b6, fw1, fb1, fw2, fb2, out);
}